// round 4
// baseline (speedup 1.0000x reference)
#include <cuda_runtime.h>
#include <cuda_bf16.h>
#include <cstdint>

#define T_STEPS 4
#define BN      16384            // B*N = 32*512
#define DIMN    512
#define FLAG_CAP (1 << 22)
#define TAU_FLAG 2e-3f

// ---------------- scratch (device globals; no allocs allowed) ----------------
__device__ __align__(16) signed char g_S[(size_t)T_STEPS * BN * DIMN];  // spikes s8 (32MB)
__device__ __align__(16) signed char g_Wl[3 * DIMN * DIMN];             // 3 int8 limbs of W*2^21
__device__ int g_nflag;
__device__ uint32_t g_flags[FLAG_CAP];

__global__ void k_reset() { g_nflag = 0; }

// ---------------- K0: exact fixed-point limb split of W (scale 2^21) ----------------
__global__ void k_split_w(const float* __restrict__ W) {
    int i = blockIdx.x * blockDim.x + threadIdx.x;
    if (i >= DIMN * DIMN) return;
    long long v = llrintf(W[i] * 2097152.0f);     // * 2^21 (exact power-2 scale)
#pragma unroll
    for (int l = 0; l < 3; ++l) {
        long long r = ((v + 64) & 127) - 64;      // balanced digit in [-64,63]
        g_Wl[l * DIMN * DIMN + i] = (signed char)r;
        v = (v - r) >> 7;                         // exact /128
    }
}

// ---------------- K1: LIF1 over T=4 (bit-exact vs reference) ----------------
__global__ void k_lif1(const float* __restrict__ in) {
    int gid = blockIdx.x * blockDim.x + threadIdx.x;   // over BN*DIMN/4
    int base = gid * 4;
    int bn = base >> 9;
    int d  = base & 511;
    float v0 = 0.f, v1 = 0.f, v2 = 0.f, v3 = 0.f;
#pragma unroll
    for (int t = 0; t < T_STEPS; ++t) {
        const float4 x = *reinterpret_cast<const float4*>(
            in + ((size_t)(t * BN + bn)) * 1024 + 512 + d);   // gate half
        v0 = v0 * 0.5f + x.x;  // v*0.5 exact -> bit-identical to reference
        v1 = v1 * 0.5f + x.y;
        v2 = v2 * 0.5f + x.z;
        v3 = v3 * 0.5f + x.w;
        char4 s;
        s.x = (v0 >= 1.0f) ? 1 : 0;
        s.y = (v1 >= 1.0f) ? 1 : 0;
        s.z = (v2 >= 1.0f) ? 1 : 0;
        s.w = (v3 >= 1.0f) ? 1 : 0;
        v0 = s.x ? 0.f : v0;
        v1 = s.y ? 0.f : v1;
        v2 = s.z ? 0.f : v2;
        v3 = s.w ? 0.f : v3;
        *reinterpret_cast<char4*>(g_S + ((size_t)(t * BN + bn)) * 512 + d) = s;
    }
}

// ---------------- asm helpers ----------------
__device__ __forceinline__ uint32_t smem_u32(const void* p) {
    uint32_t r;
    asm("{ .reg .u64 t; cvta.to.shared.u64 t, %1; cvt.u32.u64 %0, t; }" : "=r"(r) : "l"(p));
    return r;
}
__device__ __forceinline__ void cp16(uint32_t saddr, const void* g) {
    asm volatile("cp.async.cg.shared.global [%0], [%1], 16;" :: "r"(saddr), "l"(g) : "memory");
}
#define CP_COMMIT() asm volatile("cp.async.commit_group;" ::: "memory")
#define CP_WAIT(n)  asm volatile("cp.async.wait_group %0;" :: "n"(n) : "memory")

__device__ __forceinline__ void ldm_x4(uint32_t* a, uint32_t addr) {
    asm volatile("ldmatrix.sync.aligned.m8n8.x4.shared.b16 {%0,%1,%2,%3}, [%4];"
                 : "=r"(a[0]), "=r"(a[1]), "=r"(a[2]), "=r"(a[3]) : "r"(addr));
}
__device__ __forceinline__ void mma_s8(int* c, const uint32_t* a, uint32_t b0, uint32_t b1) {
    asm volatile(
        "mma.sync.aligned.m16n8k32.row.col.s32.s8.s8.s32 "
        "{%0,%1,%2,%3}, {%4,%5,%6,%7}, {%8,%9}, {%0,%1,%2,%3};"
        : "+r"(c[0]), "+r"(c[1]), "+r"(c[2]), "+r"(c[3])
        : "r"(a[0]), "r"(a[1]), "r"(a[2]), "r"(a[3]), "r"(b0), "r"(b1));
}

// ---------------- K2: exact int8-limb GEMM + LIF2 + gated multiply + tie flagging ----------------
#define M_TILE   128
#define N_TILE   64
#define K_CHUNK  64
#define B_BYTES  (3 * N_TILE * DIMN)         // 98304 (resident W limbs)
#define A_STAGE  (M_TILE * K_CHUNK)          // 8192
#define SMEM_TOTAL (B_BYTES + 2 * A_STAGE)   // 114688

__device__ __forceinline__ void load_A(uint32_t sA, const signed char* __restrict__ gA, int tid) {
    int row = tid >> 2, ch = tid & 3;
    cp16(sA + (uint32_t)(row * 64 + ((ch ^ ((row >> 1) & 3)) * 16)),
         gA + (size_t)row * 512 + ch * 16);
}

__global__ __launch_bounds__(512, 1)
void k_gemm_lif2(const float* __restrict__ in, const float* __restrict__ bvec,
                 float* __restrict__ out) {
    extern __shared__ char smem[];
    const uint32_t sB = smem_u32(smem);
    const uint32_t sAb = sB + B_BYTES;
    const int tid = threadIdx.x, wid = tid >> 5, lane = tid & 31;
    const int wm = wid & 3, wn = wid >> 2;
    const int bn0 = blockIdx.x * M_TILE;
    const int et0 = blockIdx.y * N_TILE;

    // ---- resident B: 3 limbs x [64 e-rows x 512 k-bytes], swizzled ----
#pragma unroll
    for (int i = 0; i < 12; ++i) {
        int lin = tid + i * 512;
        int limb = lin >> 11, rem = lin & 2047;
        int n = rem >> 5, kc = rem & 31;
        cp16(sB + (uint32_t)(limb * 32768 + n * 512 + ((kc ^ (n & 7)) * 16)),
             g_Wl + (size_t)limb * (DIMN * DIMN) + (size_t)(et0 + n) * 512 + kc * 16);
    }
    CP_COMMIT();

    // ---- A pipeline prologue: global chunks 0,1 (t=0) ----
    load_A(sAb,           g_S + ((size_t)bn0) * 512 + 0 * 64, tid);
    CP_COMMIT();
    load_A(sAb + A_STAGE, g_S + ((size_t)bn0) * 512 + 1 * 64, tid);
    CP_COMMIT();

    float bb[2][2];
#pragma unroll
    for (int ng = 0; ng < 2; ++ng)
#pragma unroll
        for (int q = 0; q < 2; ++q)
            bb[ng][q] = bvec[et0 + wn * 16 + ng * 8 + 2 * (lane & 3) + q];

    const int lrow = lane & 15, lch = lane >> 4;

    float v[2][2][4];
#pragma unroll
    for (int i = 0; i < 2; ++i)
#pragma unroll
        for (int ng = 0; ng < 2; ++ng)
#pragma unroll
            for (int e = 0; e < 4; ++e) v[i][ng][e] = 0.f;

    unsigned fl = 0;   // tie flags: bit = i*8 + ng*4 + h*2 + q

#pragma unroll 1
    for (int t = 0; t < T_STEPS; ++t) {
        int acc[3][2][2][4];
#pragma unroll
        for (int l = 0; l < 3; ++l)
#pragma unroll
            for (int i = 0; i < 2; ++i)
#pragma unroll
                for (int ng = 0; ng < 2; ++ng)
#pragma unroll
                    for (int e = 0; e < 4; ++e) acc[l][i][ng][e] = 0;

#pragma unroll 1
        for (int c = 0; c < 8; ++c) {
            CP_WAIT(1);
            __syncthreads();
            const uint32_t sA = sAb + (uint32_t)((c & 1) * A_STAGE);

            uint32_t a[2][2][4];
#pragma unroll
            for (int i = 0; i < 2; ++i)
#pragma unroll
                for (int ks = 0; ks < 2; ++ks) {
                    int row = wm * 32 + i * 16 + lrow;
                    int ch = ks * 2 + lch;
                    ldm_x4(a[i][ks], sA + (uint32_t)(row * 64 + ((ch ^ ((row >> 1) & 3)) * 16)));
                }

#pragma unroll
            for (int l = 0; l < 3; ++l) {
#pragma unroll
                for (int ks = 0; ks < 2; ++ks) {
                    uint32_t bf[4];
                    int n = wn * 16 + lrow;
                    int kc = c * 4 + ks * 2 + lch;
                    ldm_x4(bf, sB + (uint32_t)(l * 32768 + n * 512 + ((kc ^ (n & 7)) * 16)));
#pragma unroll
                    for (int i = 0; i < 2; ++i) {
                        mma_s8(acc[l][i][0], a[i][ks], bf[0], bf[2]);
                        mma_s8(acc[l][i][1], a[i][ks], bf[1], bf[3]);
                    }
                }
            }
            __syncthreads();
            int next = t * 8 + c + 2;
            if (next < 32) {
                int tn = next >> 3, cn = next & 7;
                load_A(sAb + (uint32_t)((c & 1) * A_STAGE),
                       g_S + ((size_t)(tn * BN + bn0)) * 512 + cn * 64, tid);
            }
            CP_COMMIT();
        }

        // ---- epilogue: exact reconstruction + bias + LIF2 + gated multiply ----
#pragma unroll
        for (int i = 0; i < 2; ++i) {
#pragma unroll
            for (int ng = 0; ng < 2; ++ng) {
#pragma unroll
                for (int h = 0; h < 2; ++h) {
                    float s[2];
#pragma unroll
                    for (int q = 0; q < 2; ++q) {
                        int e = 2 * h + q;
                        int lo = acc[0][i][ng][e] + (acc[1][i][ng][e] << 7);   // exact in int
                        float y = fmaf((float)acc[2][i][ng][e], 16384.0f, (float)lo)
                                  * 4.76837158203125e-07f;                     // * 2^-21
                        float g = y + bb[ng][q];
                        float vv = v[i][ng][e] * 0.5f + g;
                        float sp = (vv >= 1.0f) ? 1.0f : 0.0f;
                        v[i][ng][e] = vv * (1.0f - sp);
                        s[q] = sp;
                        if (fabsf(vv - 1.0f) < TAU_FLAG)
                            fl |= 1u << (i * 8 + ng * 4 + h * 2 + q);
                    }
                    int row = bn0 + wm * 32 + i * 16 + (lane >> 2) + h * 8;
                    int col = et0 + wn * 16 + ng * 8 + 2 * (lane & 3);
                    size_t grow = (size_t)(t * BN) + row;
                    const float2 o = *reinterpret_cast<const float2*>(
                        in + grow * 1024 + col);      // outputs half
                    float2 r;
                    r.x = o.x * s[0];
                    r.y = o.y * s[1];
                    *reinterpret_cast<float2*>(out + grow * 512 + col) = r;
                }
            }
        }
    }

    // ---- push flagged (bn,e) pairs for exact-replication fixup ----
    if (fl) {
#pragma unroll
        for (int i = 0; i < 2; ++i)
#pragma unroll
            for (int ng = 0; ng < 2; ++ng)
#pragma unroll
                for (int h = 0; h < 2; ++h)
#pragma unroll
                    for (int q = 0; q < 2; ++q)
                        if (fl & (1u << (i * 8 + ng * 4 + h * 2 + q))) {
                            int row = bn0 + wm * 32 + i * 16 + (lane >> 2) + h * 8;
                            int col = et0 + wn * 16 + ng * 8 + 2 * (lane & 3) + q;
                            int idx = atomicAdd(&g_nflag, 1);
                            if (idx < FLAG_CAP)
                                g_flags[idx] = (uint32_t)(row * 512 + col);
                        }
    }
}

// ---------------- K3: fixup — replicate reference fp32 chain on flagged ties ----------------
__global__ __launch_bounds__(256)
void k_fixup(const float* __restrict__ in, const float* __restrict__ W,
             const float* __restrict__ bvec, float* __restrict__ out) {
    int n = g_nflag;
    if (n > FLAG_CAP) n = FLAG_CAP;
    for (int idx = blockIdx.x * blockDim.x + threadIdx.x; idx < n;
         idx += gridDim.x * blockDim.x) {
        uint32_t key = g_flags[idx];
        int bn = key >> 9, e = key & 511;
        const float* w = W + (size_t)e * 512;
        float bias = bvec[e];
        float v = 0.f;
#pragma unroll 1
        for (int t = 0; t < T_STEPS; ++t) {
            const signed char* sp = g_S + ((size_t)(t * BN + bn)) * 512;
            float acc = 0.f;
#pragma unroll 4
            for (int d = 0; d < 512; ++d)
                acc = (sp[d] ? (acc + w[d]) : acc);   // ascending-d single-chain, as ref
            float g = acc + bias;
            float vv = v * 0.5f + g;
            float s = (vv >= 1.0f) ? 1.0f : 0.0f;
            v = vv * (1.0f - s);
            size_t grow = (size_t)(t * BN) + bn;
            out[grow * 512 + e] = in[grow * 1024 + e] * s;
        }
    }
}

// ---------------- launcher ----------------
extern "C" void kernel_launch(void* const* d_in, const int* in_sizes, int n_in,
                              void* d_out, int out_size) {
    const float* inputs = (const float*)d_in[0];   // [4,32,512,1024]
    const float* W      = (const float*)d_in[1];   // [512,512]
    const float* b      = (const float*)d_in[2];   // [512]
    float* out          = (float*)d_out;           // [4,32,512,512]

    cudaFuncSetAttribute(k_gemm_lif2, cudaFuncAttributeMaxDynamicSharedMemorySize, SMEM_TOTAL);

    k_reset<<<1, 1>>>();
    k_split_w<<<(DIMN * DIMN + 255) / 256, 256>>>(W);
    k_lif1<<<(BN * DIMN / 4 + 255) / 256, 256>>>(inputs);
    k_gemm_lif2<<<dim3(BN / M_TILE, DIMN / N_TILE), 512, SMEM_TOTAL>>>(inputs, b, out);
    k_fixup<<<256, 256>>>(inputs, W, b, out);
}

// round 5
// speedup vs baseline: 1.6023x; 1.6023x over previous
#include <cuda_runtime.h>
#include <cuda_bf16.h>
#include <cstdint>

#define T_STEPS 4
#define BN      16384            // B*N = 32*512
#define DIMN    512
#define FLAG_CAP (1 << 22)

// ---------------- scratch (device globals; no allocs allowed) ----------------
__device__ __align__(16) signed char g_S[(size_t)T_STEPS * BN * DIMN];  // spikes s8 (32MB)
__device__ __align__(16) signed char g_Wl[2 * DIMN * DIMN];             // 2 base-256 limbs of W*2^15
__device__ int g_na[T_STEPS * BN];                                      // active count per (t,row)
__device__ int g_nflag;
__device__ uint32_t g_flags[FLAG_CAP];

__global__ void k_reset() { g_nflag = 0; }

// ---------------- K0: exact base-256 limb split of W (scale 2^15) ----------------
__global__ void k_split_w(const float* __restrict__ W) {
    int i = blockIdx.x * blockDim.x + threadIdx.x;
    if (i >= DIMN * DIMN) return;
    int v = (int)llrintf(W[i] * 32768.0f);        // |W|<0.4 -> |v| < 13200
    int d0 = ((v + 128) & 255) - 128;             // balanced digit in [-128,127]
    int d1 = (v - d0) >> 8;                       // exact, |d1| <= 52
    g_Wl[i]               = (signed char)d0;
    g_Wl[DIMN * DIMN + i] = (signed char)d1;
}

// ---------------- K1: LIF1 (bit-exact) + per-row active counts ----------------
// one warp per bn row; lane covers 16 consecutive d
__global__ void k_lif1(const float* __restrict__ in) {
    int gt = blockIdx.x * blockDim.x + threadIdx.x;
    int bn = gt >> 5, lane = gt & 31;
    if (bn >= BN) return;
    int d0 = lane * 16;
    float v[16];
#pragma unroll
    for (int j = 0; j < 16; ++j) v[j] = 0.f;
#pragma unroll
    for (int t = 0; t < T_STEPS; ++t) {
        const float4* xp = reinterpret_cast<const float4*>(
            in + ((size_t)(t * BN + bn)) * 1024 + 512 + d0);
        uint32_t pk[4];
        int cnt = 0;
#pragma unroll
        for (int q = 0; q < 4; ++q) {
            float4 x = xp[q];
            float xv[4] = {x.x, x.y, x.z, x.w};
            uint32_t b = 0;
#pragma unroll
            for (int j = 0; j < 4; ++j) {
                int jj = q * 4 + j;
                v[jj] = v[jj] * 0.5f + xv[j];      // *0.5 exact -> bit-identical to ref
                int s = (v[jj] >= 1.0f) ? 1 : 0;
                v[jj] = s ? 0.f : v[jj];
                b |= (uint32_t)s << (8 * j);
                cnt += s;
            }
            pk[q] = b;
        }
        *reinterpret_cast<uint4*>(g_S + ((size_t)(t * BN + bn)) * 512 + d0) =
            make_uint4(pk[0], pk[1], pk[2], pk[3]);
#pragma unroll
        for (int off = 16; off; off >>= 1)
            cnt += __shfl_xor_sync(0xFFFFFFFF, cnt, off);
        if (lane == 0) g_na[t * BN + bn] = cnt;
    }
}

// ---------------- asm helpers ----------------
__device__ __forceinline__ uint32_t smem_u32(const void* p) {
    uint32_t r;
    asm("{ .reg .u64 t; cvta.to.shared.u64 t, %1; cvt.u32.u64 %0, t; }" : "=r"(r) : "l"(p));
    return r;
}
__device__ __forceinline__ void cp16(uint32_t saddr, const void* g) {
    asm volatile("cp.async.cg.shared.global [%0], [%1], 16;" :: "r"(saddr), "l"(g) : "memory");
}
#define CP_COMMIT() asm volatile("cp.async.commit_group;" ::: "memory")
#define CP_WAIT(n)  asm volatile("cp.async.wait_group %0;" :: "n"(n) : "memory")

__device__ __forceinline__ void ldm_x4(uint32_t* a, uint32_t addr) {
    asm volatile("ldmatrix.sync.aligned.m8n8.x4.shared.b16 {%0,%1,%2,%3}, [%4];"
                 : "=r"(a[0]), "=r"(a[1]), "=r"(a[2]), "=r"(a[3]) : "r"(addr));
}
__device__ __forceinline__ void mma_s8(int* c, const uint32_t* a, uint32_t b0, uint32_t b1) {
    asm volatile(
        "mma.sync.aligned.m16n8k32.row.col.s32.s8.s8.s32 "
        "{%0,%1,%2,%3}, {%4,%5,%6,%7}, {%8,%9}, {%0,%1,%2,%3};"
        : "+r"(c[0]), "+r"(c[1]), "+r"(c[2]), "+r"(c[3])
        : "r"(a[0]), "r"(a[1]), "r"(a[2]), "r"(a[3]), "r"(b0), "r"(b1));
}

// ---------------- K2: 2-limb exact GEMM + LIF2 + gated multiply + tie flagging ----------------
#define M_TILE   128
#define N_TILE   64
#define K_CHUNK  64
#define B_BYTES  (2 * N_TILE * DIMN)         // 65536 (resident W limbs)
#define A_STAGE  (M_TILE * K_CHUNK)          // 8192
#define SMEM_TOTAL (B_BYTES + 2 * A_STAGE)   // 81920

__device__ __forceinline__ void load_A(uint32_t sA, const signed char* __restrict__ gA, int tid) {
    int row = tid >> 2, ch = tid & 3;
    cp16(sA + (uint32_t)(row * 64 + ((ch ^ ((row >> 1) & 3)) * 16)),
         gA + (size_t)row * 512 + ch * 16);
}

__global__ __launch_bounds__(512, 1)
void k_gemm_lif2(const float* __restrict__ in, const float* __restrict__ bvec,
                 float* __restrict__ out) {
    extern __shared__ char smem[];
    const uint32_t sB = smem_u32(smem);
    const uint32_t sAb = sB + B_BYTES;
    const int tid = threadIdx.x, wid = tid >> 5, lane = tid & 31;
    const int wm = wid & 3, wn = wid >> 2;
    const int bn0 = blockIdx.x * M_TILE;
    const int et0 = blockIdx.y * N_TILE;

    // ---- resident B: 2 limbs x [64 e-rows x 512 k-bytes], swizzled ----
#pragma unroll
    for (int i = 0; i < 8; ++i) {
        int lin = tid + i * 512;
        int limb = lin >> 11, rem = lin & 2047;
        int n = rem >> 5, kc = rem & 31;
        cp16(sB + (uint32_t)(limb * 32768 + n * 512 + ((kc ^ (n & 7)) * 16)),
             g_Wl + (size_t)limb * (DIMN * DIMN) + (size_t)(et0 + n) * 512 + kc * 16);
    }
    CP_COMMIT();

    load_A(sAb,           g_S + ((size_t)bn0) * 512 + 0 * 64, tid);
    CP_COMMIT();
    load_A(sAb + A_STAGE, g_S + ((size_t)bn0) * 512 + 1 * 64, tid);
    CP_COMMIT();

    float bb[2][2];
#pragma unroll
    for (int ng = 0; ng < 2; ++ng)
#pragma unroll
        for (int q = 0; q < 2; ++q)
            bb[ng][q] = bvec[et0 + wn * 16 + ng * 8 + 2 * (lane & 3) + q];

    const int lrow = lane & 15, lch = lane >> 4;

    float v[2][2][4];
#pragma unroll
    for (int i = 0; i < 2; ++i)
#pragma unroll
        for (int ng = 0; ng < 2; ++ng)
#pragma unroll
            for (int e = 0; e < 4; ++e) v[i][ng][e] = 0.f;

    unsigned fl = 0;

#pragma unroll 1
    for (int t = 0; t < T_STEPS; ++t) {
        int acc[2][2][2][4];
#pragma unroll
        for (int l = 0; l < 2; ++l)
#pragma unroll
            for (int i = 0; i < 2; ++i)
#pragma unroll
                for (int ng = 0; ng < 2; ++ng)
#pragma unroll
                    for (int e = 0; e < 4; ++e) acc[l][i][ng][e] = 0;

#pragma unroll 1
        for (int c = 0; c < 8; ++c) {
            CP_WAIT(1);
            __syncthreads();
            const uint32_t sA = sAb + (uint32_t)((c & 1) * A_STAGE);

            uint32_t a[2][2][4];
#pragma unroll
            for (int i = 0; i < 2; ++i)
#pragma unroll
                for (int ks = 0; ks < 2; ++ks) {
                    int row = wm * 32 + i * 16 + lrow;
                    int ch = ks * 2 + lch;
                    ldm_x4(a[i][ks], sA + (uint32_t)(row * 64 + ((ch ^ ((row >> 1) & 3)) * 16)));
                }

#pragma unroll
            for (int l = 0; l < 2; ++l) {
#pragma unroll
                for (int ks = 0; ks < 2; ++ks) {
                    uint32_t bf[4];
                    int n = wn * 16 + lrow;
                    int kc = c * 4 + ks * 2 + lch;
                    ldm_x4(bf, sB + (uint32_t)(l * 32768 + n * 512 + ((kc ^ (n & 7)) * 16)));
#pragma unroll
                    for (int i = 0; i < 2; ++i) {
                        mma_s8(acc[l][i][0], a[i][ks], bf[0], bf[2]);
                        mma_s8(acc[l][i][1], a[i][ks], bf[1], bf[3]);
                    }
                }
            }
            __syncthreads();
            int next = t * 8 + c + 2;
            if (next < 32) {
                int tn = next >> 3, cn = next & 7;
                load_A(sAb + (uint32_t)((c & 1) * A_STAGE),
                       g_S + ((size_t)(tn * BN + bn0)) * 512 + cn * 64, tid);
            }
            CP_COMMIT();
        }

        // ---- epilogue: exact reconstruction + bias + LIF2 + flag + gated multiply ----
#pragma unroll
        for (int i = 0; i < 2; ++i) {
#pragma unroll
            for (int h = 0; h < 2; ++h) {
                int rowl = wm * 32 + i * 16 + (lane >> 2) + h * 8;
                // hard bound on |v - v_ref|: quant (na*2^-16) + chain rounding, x2
                float na = (float)g_na[t * BN + bn0 + rowl];
                float tau = fmaf(na, 3.0517578125e-05f, 4e-4f);
#pragma unroll
                for (int ng = 0; ng < 2; ++ng) {
                    float s[2];
#pragma unroll
                    for (int q = 0; q < 2; ++q) {
                        int e = 2 * h + q;
                        float y = fmaf((float)acc[1][i][ng][e], 256.0f,
                                       (float)acc[0][i][ng][e])
                                  * 3.0517578125e-05f;                 // * 2^-15, all exact
                        float g = y + bb[ng][q];
                        float vv = v[i][ng][e] * 0.5f + g;
                        float sp = (vv >= 1.0f) ? 1.0f : 0.0f;
                        v[i][ng][e] = vv * (1.0f - sp);
                        s[q] = sp;
                        if (fabsf(vv - 1.0f) < tau)
                            fl |= 1u << (i * 8 + ng * 4 + h * 2 + q);
                    }
                    int row = bn0 + rowl;
                    int col = et0 + wn * 16 + ng * 8 + 2 * (lane & 3);
                    size_t grow = (size_t)(t * BN) + row;
                    const float2 o = *reinterpret_cast<const float2*>(
                        in + grow * 1024 + col);
                    float2 r;
                    r.x = o.x * s[0];
                    r.y = o.y * s[1];
                    *reinterpret_cast<float2*>(out + grow * 512 + col) = r;
                }
            }
        }
    }

    if (fl) {
#pragma unroll
        for (int i = 0; i < 2; ++i)
#pragma unroll
            for (int ng = 0; ng < 2; ++ng)
#pragma unroll
                for (int h = 0; h < 2; ++h)
#pragma unroll
                    for (int q = 0; q < 2; ++q)
                        if (fl & (1u << (i * 8 + ng * 4 + h * 2 + q))) {
                            int row = bn0 + wm * 32 + i * 16 + (lane >> 2) + h * 8;
                            int col = et0 + wn * 16 + ng * 8 + 2 * (lane & 3) + q;
                            int idx = atomicAdd(&g_nflag, 1);
                            if (idx < FLAG_CAP)
                                g_flags[idx] = (uint32_t)(row * 512 + col);
                        }
    }
}

// ---------------- K3: fixup — replicate reference fp32 chain on flagged ties ----------------
__global__ __launch_bounds__(256)
void k_fixup(const float* __restrict__ in, const float* __restrict__ W,
             const float* __restrict__ bvec, float* __restrict__ out) {
    int n = g_nflag;
    if (n > FLAG_CAP) n = FLAG_CAP;
    for (int idx = blockIdx.x * blockDim.x + threadIdx.x; idx < n;
         idx += gridDim.x * blockDim.x) {
        uint32_t key = g_flags[idx];
        int bn = (int)(key >> 9), e = (int)(key & 511);
        const float* w = W + (size_t)e * 512;
        float bias = bvec[e];
        float v = 0.f;
#pragma unroll 1
        for (int t = 0; t < T_STEPS; ++t) {
            const uint4* sp4 = reinterpret_cast<const uint4*>(
                g_S + ((size_t)(t * BN + bn)) * 512);
            float acc = 0.f;
#pragma unroll 1
            for (int g16 = 0; g16 < 32; ++g16) {
                uint4 m = sp4[g16];
                const float* wg = w + g16 * 16;
                uint32_t mw[4] = {m.x, m.y, m.z, m.w};
#pragma unroll
                for (int u = 0; u < 4; ++u)
#pragma unroll
                    for (int j = 0; j < 4; ++j)
                        if ((mw[u] >> (8 * j)) & 1u)
                            acc = acc + wg[u * 4 + j];   // ascending-d single chain
            }
            float g = acc + bias;
            float vv = v * 0.5f + g;
            float s = (vv >= 1.0f) ? 1.0f : 0.0f;
            v = vv * (1.0f - s);
            size_t grow = (size_t)(t * BN) + bn;
            out[grow * 512 + e] = in[grow * 1024 + e] * s;
        }
    }
}

// ---------------- launcher ----------------
extern "C" void kernel_launch(void* const* d_in, const int* in_sizes, int n_in,
                              void* d_out, int out_size) {
    const float* inputs = (const float*)d_in[0];   // [4,32,512,1024]
    const float* W      = (const float*)d_in[1];   // [512,512]
    const float* b      = (const float*)d_in[2];   // [512]
    float* out          = (float*)d_out;           // [4,32,512,512]

    cudaFuncSetAttribute(k_gemm_lif2, cudaFuncAttributeMaxDynamicSharedMemorySize, SMEM_TOTAL);

    k_reset<<<1, 1>>>();
    k_split_w<<<(DIMN * DIMN + 255) / 256, 256>>>(W);
    k_lif1<<<(BN * 32 + 255) / 256, 256>>>(inputs);
    k_gemm_lif2<<<dim3(BN / M_TILE, DIMN / N_TILE), 512, SMEM_TOTAL>>>(inputs, b, out);
    k_fixup<<<256, 256>>>(inputs, W, b, out);
}

// round 6
// speedup vs baseline: 1.6484x; 1.0288x over previous
#include <cuda_runtime.h>
#include <cuda_bf16.h>
#include <cstdint>

#define T_STEPS 4
#define BN      16384            // B*N = 32*512
#define DIMN    512
#define FLAG_CAP (1 << 22)

// ---------------- scratch (device globals; no allocs allowed) ----------------
__device__ __align__(16) signed char g_S[(size_t)T_STEPS * BN * DIMN];  // spikes s8 (32MB)
__device__ __align__(16) signed char g_Wl[2 * DIMN * DIMN];             // 2 base-256 limbs of W*2^15
__device__ __align__(16) int g_na[T_STEPS * BN];                        // active count per (t,row)
__device__ int g_nflag;
__device__ uint32_t g_flags[FLAG_CAP];

// ---------------- K0: exact base-256 limb split of W (+ flag-counter reset) ----------------
__global__ void k_split_w(const float* __restrict__ W) {
    int i = blockIdx.x * blockDim.x + threadIdx.x;
    if (i == 0) g_nflag = 0;
    if (i >= DIMN * DIMN) return;
    int v = (int)llrintf(W[i] * 32768.0f);        // |W|<0.4 -> |v| < 13200
    int d0 = ((v + 128) & 255) - 128;             // balanced digit in [-128,127]
    int d1 = (v - d0) >> 8;                       // exact, |d1| <= 52
    g_Wl[i]               = (signed char)d0;
    g_Wl[DIMN * DIMN + i] = (signed char)d1;
}

// ---------------- K1: LIF1 (bit-exact) + per-row active counts ----------------
__global__ void k_lif1(const float* __restrict__ in) {
    int gt = blockIdx.x * blockDim.x + threadIdx.x;
    int bn = gt >> 5, lane = gt & 31;
    if (bn >= BN) return;
    int d0 = lane * 16;
    float v[16];
#pragma unroll
    for (int j = 0; j < 16; ++j) v[j] = 0.f;
#pragma unroll
    for (int t = 0; t < T_STEPS; ++t) {
        const float4* xp = reinterpret_cast<const float4*>(
            in + ((size_t)(t * BN + bn)) * 1024 + 512 + d0);
        uint32_t pk[4];
        int cnt = 0;
#pragma unroll
        for (int q = 0; q < 4; ++q) {
            float4 x = xp[q];
            float xv[4] = {x.x, x.y, x.z, x.w};
            uint32_t b = 0;
#pragma unroll
            for (int j = 0; j < 4; ++j) {
                int jj = q * 4 + j;
                v[jj] = v[jj] * 0.5f + xv[j];      // *0.5 exact -> bit-identical to ref
                int s = (v[jj] >= 1.0f) ? 1 : 0;
                v[jj] = s ? 0.f : v[jj];
                b |= (uint32_t)s << (8 * j);
                cnt += s;
            }
            pk[q] = b;
        }
        *reinterpret_cast<uint4*>(g_S + ((size_t)(t * BN + bn)) * 512 + d0) =
            make_uint4(pk[0], pk[1], pk[2], pk[3]);
#pragma unroll
        for (int off = 16; off; off >>= 1)
            cnt += __shfl_xor_sync(0xFFFFFFFF, cnt, off);
        if (lane == 0) g_na[t * BN + bn] = cnt;
    }
}

// ---------------- asm helpers ----------------
__device__ __forceinline__ uint32_t smem_u32(const void* p) {
    uint32_t r;
    asm("{ .reg .u64 t; cvta.to.shared.u64 t, %1; cvt.u32.u64 %0, t; }" : "=r"(r) : "l"(p));
    return r;
}
__device__ __forceinline__ void cp16(uint32_t saddr, const void* g) {
    asm volatile("cp.async.cg.shared.global [%0], [%1], 16;" :: "r"(saddr), "l"(g) : "memory");
}
#define CP_COMMIT() asm volatile("cp.async.commit_group;" ::: "memory")
#define CP_WAIT(n)  asm volatile("cp.async.wait_group %0;" :: "n"(n) : "memory")

__device__ __forceinline__ void ldm_x4(uint32_t* a, uint32_t addr) {
    asm volatile("ldmatrix.sync.aligned.m8n8.x4.shared.b16 {%0,%1,%2,%3}, [%4];"
                 : "=r"(a[0]), "=r"(a[1]), "=r"(a[2]), "=r"(a[3]) : "r"(addr));
}
__device__ __forceinline__ void mma_s8(int* c, const uint32_t* a, uint32_t b0, uint32_t b1) {
    asm volatile(
        "mma.sync.aligned.m16n8k32.row.col.s32.s8.s8.s32 "
        "{%0,%1,%2,%3}, {%4,%5,%6,%7}, {%8,%9}, {%0,%1,%2,%3};"
        : "+r"(c[0]), "+r"(c[1]), "+r"(c[2]), "+r"(c[3])
        : "r"(a[0]), "r"(a[1]), "r"(a[2]), "r"(a[3]), "r"(b0), "r"(b1));
}

// ---------------- K2: 2-limb exact GEMM + LIF2 + gated multiply + tie flagging ----------------
#define M_TILE   128
#define N_TILE   64
#define K_CHUNK  64
#define B_BYTES  (2 * N_TILE * DIMN)          // 65536 (resident W limbs)
#define A_STAGE  (M_TILE * K_CHUNK)           // 8192
#define IN_OFF   (B_BYTES + 2 * A_STAGE)      // 81920: in-tile [128 x 64] f32 (32KB)
#define NA_OFF   (IN_OFF + M_TILE * N_TILE * 4)  // 114688: na[128]
#define SMEM_TOTAL (NA_OFF + 512)             // 115200

__device__ __forceinline__ void load_A(uint32_t sA, const signed char* __restrict__ gA, int tid) {
    int row = tid >> 2, ch = tid & 3;
    cp16(sA + (uint32_t)(row * 64 + ((ch ^ ((row >> 1) & 3)) * 16)),
         gA + (size_t)row * 512 + ch * 16);
}

__global__ __launch_bounds__(512, 1)
void k_gemm_lif2(const float* __restrict__ in, const float* __restrict__ bvec,
                 float* __restrict__ out) {
    extern __shared__ char smem[];
    const uint32_t sB = smem_u32(smem);
    const uint32_t sAb = sB + B_BYTES;
    const int tid = threadIdx.x, wid = tid >> 5, lane = tid & 31;
    const int wm = wid & 3, wn = wid >> 2;
    const int bn0 = blockIdx.x * M_TILE;
    const int et0 = blockIdx.y * N_TILE;

    // ---- resident B: 2 limbs x [64 e-rows x 512 k-bytes], swizzled ----
#pragma unroll
    for (int i = 0; i < 8; ++i) {
        int lin = tid + i * 512;
        int limb = lin >> 11, rem = lin & 2047;
        int n = rem >> 5, kc = rem & 31;
        cp16(sB + (uint32_t)(limb * 32768 + n * 512 + ((kc ^ (n & 7)) * 16)),
             g_Wl + (size_t)limb * (DIMN * DIMN) + (size_t)(et0 + n) * 512 + kc * 16);
    }
    CP_COMMIT();

    load_A(sAb,           g_S + ((size_t)bn0) * 512 + 0 * 64, tid);
    CP_COMMIT();
    load_A(sAb + A_STAGE, g_S + ((size_t)bn0) * 512 + 1 * 64, tid);
    CP_COMMIT();

    float bb[2][2];
#pragma unroll
    for (int ng = 0; ng < 2; ++ng)
#pragma unroll
        for (int q = 0; q < 2; ++q)
            bb[ng][q] = bvec[et0 + wn * 16 + ng * 8 + 2 * (lane & 3) + q];

    const int lrow = lane & 15, lch = lane >> 4;
    const float* inS = (const float*)(smem + IN_OFF);
    const int*   naS = (const int*)(smem + NA_OFF);

    float v[2][2][4];
#pragma unroll
    for (int i = 0; i < 2; ++i)
#pragma unroll
        for (int ng = 0; ng < 2; ++ng)
#pragma unroll
            for (int e = 0; e < 4; ++e) v[i][ng][e] = 0.f;

    unsigned fl = 0;

#pragma unroll 1
    for (int t = 0; t < T_STEPS; ++t) {
        int acc[2][2][2][4];
#pragma unroll
        for (int l = 0; l < 2; ++l)
#pragma unroll
            for (int i = 0; i < 2; ++i)
#pragma unroll
                for (int ng = 0; ng < 2; ++ng)
#pragma unroll
                    for (int e = 0; e < 4; ++e) acc[l][i][ng][e] = 0;

#pragma unroll 1
        for (int c = 0; c < 8; ++c) {
            CP_WAIT(1);
            __syncthreads();
            const uint32_t sA = sAb + (uint32_t)((c & 1) * A_STAGE);

            uint32_t a[2][2][4];
#pragma unroll
            for (int i = 0; i < 2; ++i)
#pragma unroll
                for (int ks = 0; ks < 2; ++ks) {
                    int row = wm * 32 + i * 16 + lrow;
                    int ch = ks * 2 + lch;
                    ldm_x4(a[i][ks], sA + (uint32_t)(row * 64 + ((ch ^ ((row >> 1) & 3)) * 16)));
                }

#pragma unroll
            for (int l = 0; l < 2; ++l) {
#pragma unroll
                for (int ks = 0; ks < 2; ++ks) {
                    uint32_t bf[4];
                    int n = wn * 16 + lrow;
                    int kc = c * 4 + ks * 2 + lch;
                    ldm_x4(bf, sB + (uint32_t)(l * 32768 + n * 512 + ((kc ^ (n & 7)) * 16)));
#pragma unroll
                    for (int i = 0; i < 2; ++i) {
                        mma_s8(acc[l][i][0], a[i][ks], bf[0], bf[2]);
                        mma_s8(acc[l][i][1], a[i][ks], bf[1], bf[3]);
                    }
                }
            }
            __syncthreads();

            if (c == 0) {
                // prefetch this t's outputs-tile + na row into smem
                // (commits with chunk c+2's group; complete+synced by c=2, used after c=7)
                const float* gin = in + ((size_t)(t * BN + bn0)) * 1024 + et0;
#pragma unroll
                for (int i2 = 0; i2 < 4; ++i2) {
                    int lin = i2 * 512 + tid;
                    int r = lin >> 4, cg = lin & 15;
                    cp16(sB + (uint32_t)(IN_OFF + r * 256 + cg * 16),
                         gin + (size_t)r * 1024 + cg * 4);
                }
                if (tid < 32)
                    cp16(sB + (uint32_t)(NA_OFF + tid * 16), g_na + t * BN + bn0 + tid * 4);
            }
            int next = t * 8 + c + 2;
            if (next < 32) {
                int tn = next >> 3, cn = next & 7;
                load_A(sAb + (uint32_t)((c & 1) * A_STAGE),
                       g_S + ((size_t)(tn * BN + bn0)) * 512 + cn * 64, tid);
            }
            CP_COMMIT();
        }

        // ---- epilogue: exact reconstruction + bias + LIF2 + flag + gated multiply ----
#pragma unroll
        for (int i = 0; i < 2; ++i) {
#pragma unroll
            for (int h = 0; h < 2; ++h) {
                int rowl = wm * 32 + i * 16 + (lane >> 2) + h * 8;
                // hard bound on |v - v_ref|: quant (na*2^-16) + chain rounding, x2
                float na = (float)naS[rowl];
                float tau = fmaf(na, 3.0517578125e-05f, 4e-4f);
#pragma unroll
                for (int ng = 0; ng < 2; ++ng) {
                    int coll = wn * 16 + ng * 8 + 2 * (lane & 3);
                    float s[2];
#pragma unroll
                    for (int q = 0; q < 2; ++q) {
                        int e = 2 * h + q;
                        float y = fmaf((float)acc[1][i][ng][e], 256.0f,
                                       (float)acc[0][i][ng][e])
                                  * 3.0517578125e-05f;                 // * 2^-15, all exact
                        float g = y + bb[ng][q];
                        float vv = v[i][ng][e] * 0.5f + g;
                        float sp = (vv >= 1.0f) ? 1.0f : 0.0f;
                        v[i][ng][e] = vv * (1.0f - sp);
                        s[q] = sp;
                        if (fabsf(vv - 1.0f) < tau)
                            fl |= 1u << (i * 8 + ng * 4 + h * 2 + q);
                    }
                    const float2 o = *reinterpret_cast<const float2*>(inS + rowl * 64 + coll);
                    size_t grow = (size_t)(t * BN) + bn0 + rowl;
                    float2 r;
                    r.x = o.x * s[0];
                    r.y = o.y * s[1];
                    *reinterpret_cast<float2*>(out + grow * 512 + et0 + coll) = r;
                }
            }
        }
    }

    if (fl) {
#pragma unroll
        for (int i = 0; i < 2; ++i)
#pragma unroll
            for (int ng = 0; ng < 2; ++ng)
#pragma unroll
                for (int h = 0; h < 2; ++h)
#pragma unroll
                    for (int q = 0; q < 2; ++q)
                        if (fl & (1u << (i * 8 + ng * 4 + h * 2 + q))) {
                            int row = bn0 + wm * 32 + i * 16 + (lane >> 2) + h * 8;
                            int col = et0 + wn * 16 + ng * 8 + 2 * (lane & 3) + q;
                            int idx = atomicAdd(&g_nflag, 1);
                            if (idx < FLAG_CAP)
                                g_flags[idx] = (uint32_t)(row * 512 + col);
                        }
    }
}

// ---------------- K3: fixup — replicate reference fp32 chain on flagged ties ----------------
__global__ __launch_bounds__(256)
void k_fixup(const float* __restrict__ in, const float* __restrict__ W,
             const float* __restrict__ bvec, float* __restrict__ out) {
    int n = g_nflag;
    if (n > FLAG_CAP) n = FLAG_CAP;
    for (int idx = blockIdx.x * blockDim.x + threadIdx.x; idx < n;
         idx += gridDim.x * blockDim.x) {
        uint32_t key = g_flags[idx];
        int bn = (int)(key >> 9), e = (int)(key & 511);
        const float* w = W + (size_t)e * 512;
        float bias = bvec[e];
        float v = 0.f;
#pragma unroll 1
        for (int t = 0; t < T_STEPS; ++t) {
            const uint4* sp4 = reinterpret_cast<const uint4*>(
                g_S + ((size_t)(t * BN + bn)) * 512);
            float acc = 0.f;
#pragma unroll 1
            for (int g16 = 0; g16 < 32; ++g16) {
                uint4 m = sp4[g16];
                const float* wg = w + g16 * 16;
                uint32_t mw[4] = {m.x, m.y, m.z, m.w};
#pragma unroll
                for (int u = 0; u < 4; ++u)
#pragma unroll
                    for (int j = 0; j < 4; ++j)
                        if ((mw[u] >> (8 * j)) & 1u)
                            acc = acc + wg[u * 4 + j];   // ascending-d single chain
            }
            float g = acc + bias;
            float vv = v * 0.5f + g;
            float s = (vv >= 1.0f) ? 1.0f : 0.0f;
            v = vv * (1.0f - s);
            size_t grow = (size_t)(t * BN) + bn;
            out[grow * 512 + e] = in[grow * 1024 + e] * s;
        }
    }
}

// ---------------- launcher ----------------
extern "C" void kernel_launch(void* const* d_in, const int* in_sizes, int n_in,
                              void* d_out, int out_size) {
    const float* inputs = (const float*)d_in[0];   // [4,32,512,1024]
    const float* W      = (const float*)d_in[1];   // [512,512]
    const float* b      = (const float*)d_in[2];   // [512]
    float* out          = (float*)d_out;           // [4,32,512,512]

    cudaFuncSetAttribute(k_gemm_lif2, cudaFuncAttributeMaxDynamicSharedMemorySize, SMEM_TOTAL);

    k_split_w<<<(DIMN * DIMN + 255) / 256, 256>>>(W);
    k_lif1<<<(BN * 32 + 255) / 256, 256>>>(inputs);
    k_gemm_lif2<<<dim3(BN / M_TILE, DIMN / N_TILE), 512, SMEM_TOTAL>>>(inputs, b, out);
    k_fixup<<<256, 256>>>(inputs, W, b, out);
}

// round 7
// speedup vs baseline: 1.8787x; 1.1397x over previous
#include <cuda_runtime.h>
#include <cuda_bf16.h>
#include <cstdint>

#define T_STEPS 4
#define BN      16384            // B*N = 32*512
#define DIMN    512
#define FLAG_CAP (1 << 22)

// ---------------- scratch (device globals; no allocs allowed) ----------------
__device__ __align__(16) signed char g_S[(size_t)T_STEPS * BN * DIMN];  // spikes s8 (32MB)
__device__ __align__(16) signed char g_Wl[2 * DIMN * DIMN];             // 2 base-256 limbs of W*2^16
__device__ __align__(16) int g_na[T_STEPS * BN];                        // active count per (t,row)
__device__ int g_nflag;
__device__ uint32_t g_flags[FLAG_CAP];

// ---------------- K0: exact base-256 limb split of W*2^16 (+ flag reset) ----------------
__global__ void k_split_w(const float* __restrict__ W) {
    int i = blockIdx.x * blockDim.x + threadIdx.x;
    if (i == 0) g_nflag = 0;
    if (i >= DIMN * DIMN) return;
    int v = (int)llrintf(W[i] * 65536.0f);        // |W|<0.45 -> |v| < 29500 (safe)
    int d0 = ((v + 128) & 255) - 128;             // balanced digit in [-128,127]
    int d1 = (v - d0) >> 8;                       // exact, |d1| <= 116
    g_Wl[i]               = (signed char)d0;
    g_Wl[DIMN * DIMN + i] = (signed char)d1;
}

// ---------------- K1: LIF1 (bit-exact) + per-row active counts ----------------
__global__ void k_lif1(const float* __restrict__ in) {
    int gt = blockIdx.x * blockDim.x + threadIdx.x;
    int bn = gt >> 5, lane = gt & 31;
    if (bn >= BN) return;
    int d0 = lane * 16;
    float v[16];
#pragma unroll
    for (int j = 0; j < 16; ++j) v[j] = 0.f;
#pragma unroll
    for (int t = 0; t < T_STEPS; ++t) {
        const float4* xp = reinterpret_cast<const float4*>(
            in + ((size_t)(t * BN + bn)) * 1024 + 512 + d0);
        uint32_t pk[4];
        int cnt = 0;
#pragma unroll
        for (int q = 0; q < 4; ++q) {
            float4 x = xp[q];
            float xv[4] = {x.x, x.y, x.z, x.w};
            uint32_t b = 0;
#pragma unroll
            for (int j = 0; j < 4; ++j) {
                int jj = q * 4 + j;
                v[jj] = v[jj] * 0.5f + xv[j];      // *0.5 exact -> bit-identical to ref
                int s = (v[jj] >= 1.0f) ? 1 : 0;
                v[jj] = s ? 0.f : v[jj];
                b |= (uint32_t)s << (8 * j);
                cnt += s;
            }
            pk[q] = b;
        }
        *reinterpret_cast<uint4*>(g_S + ((size_t)(t * BN + bn)) * 512 + d0) =
            make_uint4(pk[0], pk[1], pk[2], pk[3]);
#pragma unroll
        for (int off = 16; off; off >>= 1)
            cnt += __shfl_xor_sync(0xFFFFFFFF, cnt, off);
        if (lane == 0) g_na[t * BN + bn] = cnt;
    }
}

// ---------------- asm helpers ----------------
__device__ __forceinline__ uint32_t smem_u32(const void* p) {
    uint32_t r;
    asm("{ .reg .u64 t; cvta.to.shared.u64 t, %1; cvt.u32.u64 %0, t; }" : "=r"(r) : "l"(p));
    return r;
}
__device__ __forceinline__ void cp16(uint32_t saddr, const void* g) {
    asm volatile("cp.async.cg.shared.global [%0], [%1], 16;" :: "r"(saddr), "l"(g) : "memory");
}
#define CP_COMMIT() asm volatile("cp.async.commit_group;" ::: "memory")
#define CP_WAIT(n)  asm volatile("cp.async.wait_group %0;" :: "n"(n) : "memory")

__device__ __forceinline__ void ldm_x4(uint32_t* a, uint32_t addr) {
    asm volatile("ldmatrix.sync.aligned.m8n8.x4.shared.b16 {%0,%1,%2,%3}, [%4];"
                 : "=r"(a[0]), "=r"(a[1]), "=r"(a[2]), "=r"(a[3]) : "r"(addr));
}
__device__ __forceinline__ void mma_s8(int* c, const uint32_t* a, uint32_t b0, uint32_t b1) {
    asm volatile(
        "mma.sync.aligned.m16n8k32.row.col.s32.s8.s8.s32 "
        "{%0,%1,%2,%3}, {%4,%5,%6,%7}, {%8,%9}, {%0,%1,%2,%3};"
        : "+r"(c[0]), "+r"(c[1]), "+r"(c[2]), "+r"(c[3])
        : "r"(a[0]), "r"(a[1]), "r"(a[2]), "r"(a[3]), "r"(b0), "r"(b1));
}

// ---------------- K2: 2-limb exact GEMM + LIF2 + gated multiply + tie flagging ----------------
#define M_TILE   128
#define N_TILE   64
#define K_CHUNK  64
#define B_BYTES  (2 * N_TILE * DIMN)          // 65536 (resident W limbs)
#define A_STAGE  (M_TILE * K_CHUNK)           // 8192
#define IN_OFF   (B_BYTES + 2 * A_STAGE)      // 81920: in-tile [128 x 64] f32 (32KB)
#define NA_OFF   (IN_OFF + M_TILE * N_TILE * 4)  // 114688: na[128]
#define SMEM_TOTAL (NA_OFF + 512)             // 115200

__device__ __forceinline__ void load_A(uint32_t sA, const signed char* __restrict__ gA, int tid) {
    int row = tid >> 2, ch = tid & 3;
    cp16(sA + (uint32_t)(row * 64 + ((ch ^ ((row >> 1) & 3)) * 16)),
         gA + (size_t)row * 512 + ch * 16);
}

__global__ __launch_bounds__(512, 1)
void k_gemm_lif2(const float* __restrict__ in, const float* __restrict__ bvec,
                 float* __restrict__ out) {
    extern __shared__ char smem[];
    const uint32_t sB = smem_u32(smem);
    const uint32_t sAb = sB + B_BYTES;
    const int tid = threadIdx.x, wid = tid >> 5, lane = tid & 31;
    const int wm = wid & 3, wn = wid >> 2;
    const int bn0 = blockIdx.x * M_TILE;
    const int et0 = blockIdx.y * N_TILE;

    // ---- resident B: 2 limbs x [64 e-rows x 512 k-bytes], swizzled ----
#pragma unroll
    for (int i = 0; i < 8; ++i) {
        int lin = tid + i * 512;
        int limb = lin >> 11, rem = lin & 2047;
        int n = rem >> 5, kc = rem & 31;
        cp16(sB + (uint32_t)(limb * 32768 + n * 512 + ((kc ^ (n & 7)) * 16)),
             g_Wl + (size_t)limb * (DIMN * DIMN) + (size_t)(et0 + n) * 512 + kc * 16);
    }
    CP_COMMIT();

    load_A(sAb,           g_S + ((size_t)bn0) * 512 + 0 * 64, tid);
    CP_COMMIT();
    load_A(sAb + A_STAGE, g_S + ((size_t)bn0) * 512 + 1 * 64, tid);
    CP_COMMIT();

    float bb[2][2];
#pragma unroll
    for (int ng = 0; ng < 2; ++ng)
#pragma unroll
        for (int q = 0; q < 2; ++q)
            bb[ng][q] = bvec[et0 + wn * 16 + ng * 8 + 2 * (lane & 3) + q];

    const int lrow = lane & 15, lch = lane >> 4;
    const float* inS = (const float*)(smem + IN_OFF);
    const int*   naS = (const int*)(smem + NA_OFF);

    float v[2][2][4];
#pragma unroll
    for (int i = 0; i < 2; ++i)
#pragma unroll
        for (int ng = 0; ng < 2; ++ng)
#pragma unroll
            for (int e = 0; e < 4; ++e) v[i][ng][e] = 0.f;

    unsigned fl = 0;

#pragma unroll 1
    for (int t = 0; t < T_STEPS; ++t) {
        int acc[2][2][2][4];
#pragma unroll
        for (int l = 0; l < 2; ++l)
#pragma unroll
            for (int i = 0; i < 2; ++i)
#pragma unroll
                for (int ng = 0; ng < 2; ++ng)
#pragma unroll
                    for (int e = 0; e < 4; ++e) acc[l][i][ng][e] = 0;

#pragma unroll 1
        for (int c = 0; c < 8; ++c) {
            CP_WAIT(1);
            __syncthreads();
            const uint32_t sA = sAb + (uint32_t)((c & 1) * A_STAGE);

            uint32_t a[2][2][4];
#pragma unroll
            for (int i = 0; i < 2; ++i)
#pragma unroll
                for (int ks = 0; ks < 2; ++ks) {
                    int row = wm * 32 + i * 16 + lrow;
                    int ch = ks * 2 + lch;
                    ldm_x4(a[i][ks], sA + (uint32_t)(row * 64 + ((ch ^ ((row >> 1) & 3)) * 16)));
                }

#pragma unroll
            for (int l = 0; l < 2; ++l) {
#pragma unroll
                for (int ks = 0; ks < 2; ++ks) {
                    uint32_t bf[4];
                    int n = wn * 16 + lrow;
                    int kc = c * 4 + ks * 2 + lch;
                    ldm_x4(bf, sB + (uint32_t)(l * 32768 + n * 512 + ((kc ^ (n & 7)) * 16)));
#pragma unroll
                    for (int i = 0; i < 2; ++i) {
                        mma_s8(acc[l][i][0], a[i][ks], bf[0], bf[2]);
                        mma_s8(acc[l][i][1], a[i][ks], bf[1], bf[3]);
                    }
                }
            }
            __syncthreads();

            if (c == 0) {
                // prefetch this t's outputs-tile + na row into smem
                const float* gin = in + ((size_t)(t * BN + bn0)) * 1024 + et0;
#pragma unroll
                for (int i2 = 0; i2 < 4; ++i2) {
                    int lin = i2 * 512 + tid;
                    int r = lin >> 4, cg = lin & 15;
                    cp16(sB + (uint32_t)(IN_OFF + r * 256 + cg * 16),
                         gin + (size_t)r * 1024 + cg * 4);
                }
                if (tid < 32)
                    cp16(sB + (uint32_t)(NA_OFF + tid * 16), g_na + t * BN + bn0 + tid * 4);
            }
            int next = t * 8 + c + 2;
            if (next < 32) {
                int tn = next >> 3, cn = next & 7;
                load_A(sAb + (uint32_t)((c & 1) * A_STAGE),
                       g_S + ((size_t)(tn * BN + bn0)) * 512 + cn * 64, tid);
            }
            CP_COMMIT();
        }

        // ---- epilogue: exact reconstruction + bias + LIF2 + flag + gated multiply ----
#pragma unroll
        for (int i = 0; i < 2; ++i) {
#pragma unroll
            for (int h = 0; h < 2; ++h) {
                int rowl = wm * 32 + i * 16 + (lane >> 2) + h * 8;
                // hard bound on |v - v_ref|: quant (na*2^-17 half-ulp, x2 membrane) + chain
                float na = (float)naS[rowl];
                float tau = fmaf(na, 1.52587890625e-05f, 4e-4f);
#pragma unroll
                for (int ng = 0; ng < 2; ++ng) {
                    int coll = wn * 16 + ng * 8 + 2 * (lane & 3);
                    float s[2];
#pragma unroll
                    for (int q = 0; q < 2; ++q) {
                        int e = 2 * h + q;
                        float y = fmaf((float)acc[1][i][ng][e], 256.0f,
                                       (float)acc[0][i][ng][e])
                                  * 1.52587890625e-05f;                // * 2^-16, all exact
                        float g = y + bb[ng][q];
                        float vv = v[i][ng][e] * 0.5f + g;
                        float sp = (vv >= 1.0f) ? 1.0f : 0.0f;
                        v[i][ng][e] = vv * (1.0f - sp);
                        s[q] = sp;
                        if (fabsf(vv - 1.0f) < tau)
                            fl |= 1u << (i * 8 + ng * 4 + h * 2 + q);
                    }
                    const float2 o = *reinterpret_cast<const float2*>(inS + rowl * 64 + coll);
                    size_t grow = (size_t)(t * BN) + bn0 + rowl;
                    float2 r;
                    r.x = o.x * s[0];
                    r.y = o.y * s[1];
                    *reinterpret_cast<float2*>(out + grow * 512 + et0 + coll) = r;
                }
            }
        }
    }

    if (fl) {
#pragma unroll
        for (int i = 0; i < 2; ++i)
#pragma unroll
            for (int ng = 0; ng < 2; ++ng)
#pragma unroll
                for (int h = 0; h < 2; ++h)
#pragma unroll
                    for (int q = 0; q < 2; ++q)
                        if (fl & (1u << (i * 8 + ng * 4 + h * 2 + q))) {
                            int row = bn0 + wm * 32 + i * 16 + (lane >> 2) + h * 8;
                            int col = et0 + wn * 16 + ng * 8 + 2 * (lane & 3) + q;
                            int idx = atomicAdd(&g_nflag, 1);
                            if (idx < FLAG_CAP)
                                g_flags[idx] = (uint32_t)(row * 512 + col);
                        }
    }
}

// ---------------- K3: fixup — replicate reference fp32 chain on flagged ties ----------------
// 4 independent per-t add-chains interleaved in registers (4-way ILP), W row loaded once.
__global__ __launch_bounds__(256)
void k_fixup(const float* __restrict__ in, const float* __restrict__ W,
             const float* __restrict__ bvec, float* __restrict__ out) {
    int n = g_nflag;
    if (n > FLAG_CAP) n = FLAG_CAP;
    for (int idx = blockIdx.x * blockDim.x + threadIdx.x; idx < n;
         idx += gridDim.x * blockDim.x) {
        uint32_t key = g_flags[idx];
        int bn = (int)(key >> 9), e = (int)(key & 511);
        const float4* w4 = reinterpret_cast<const float4*>(W + (size_t)e * 512);
        float bias = bvec[e];

        float acc[T_STEPS];
#pragma unroll
        for (int t = 0; t < T_STEPS; ++t) acc[t] = 0.f;

#pragma unroll 1
        for (int g16 = 0; g16 < 32; ++g16) {
            uint4 m[T_STEPS];
#pragma unroll
            for (int t = 0; t < T_STEPS; ++t)
                m[t] = reinterpret_cast<const uint4*>(
                    g_S + ((size_t)(t * BN + bn)) * 512)[g16];
            float4 wv[4];
#pragma unroll
            for (int u = 0; u < 4; ++u) wv[u] = w4[g16 * 4 + u];
#pragma unroll
            for (int u = 0; u < 4; ++u) {
                uint32_t mw[T_STEPS] = {
                    (&m[0].x)[u], (&m[1].x)[u], (&m[2].x)[u], (&m[3].x)[u]};
                const float wj[4] = {wv[u].x, wv[u].y, wv[u].z, wv[u].w};
#pragma unroll
                for (int j = 0; j < 4; ++j) {
#pragma unroll
                    for (int t = 0; t < T_STEPS; ++t)
                        acc[t] += ((mw[t] >> (8 * j)) & 1u) ? wj[j] : 0.0f;
                }
            }
        }

        float v = 0.f;
#pragma unroll
        for (int t = 0; t < T_STEPS; ++t) {
            float g = acc[t] + bias;
            float vv = v * 0.5f + g;
            float s = (vv >= 1.0f) ? 1.0f : 0.0f;
            v = vv * (1.0f - s);
            size_t grow = (size_t)(t * BN) + bn;
            out[grow * 512 + e] = in[grow * 1024 + e] * s;
        }
    }
}

// ---------------- launcher ----------------
extern "C" void kernel_launch(void* const* d_in, const int* in_sizes, int n_in,
                              void* d_out, int out_size) {
    const float* inputs = (const float*)d_in[0];   // [4,32,512,1024]
    const float* W      = (const float*)d_in[1];   // [512,512]
    const float* b      = (const float*)d_in[2];   // [512]
    float* out          = (float*)d_out;           // [4,32,512,512]

    cudaFuncSetAttribute(k_gemm_lif2, cudaFuncAttributeMaxDynamicSharedMemorySize, SMEM_TOTAL);

    k_split_w<<<(DIMN * DIMN + 255) / 256, 256>>>(W);
    k_lif1<<<(BN * 32 + 255) / 256, 256>>>(inputs);
    k_gemm_lif2<<<dim3(BN / M_TILE, DIMN / N_TILE), 512, SMEM_TOTAL>>>(inputs, b, out);
    k_fixup<<<768, 256>>>(inputs, W, b, out);
}

// round 8
// speedup vs baseline: 2.0017x; 1.0655x over previous
#include <cuda_runtime.h>
#include <cuda_bf16.h>
#include <cstdint>

#define T_STEPS 4
#define BN      16384            // B*N = 32*512
#define DIMN    512
#define FLAG_CAP (1 << 22)

// ---------------- scratch (device globals; no allocs allowed) ----------------
__device__ __align__(16) signed char g_S[(size_t)T_STEPS * BN * DIMN];  // spikes s8 (32MB)
__device__ __align__(16) signed char g_Wl[2 * DIMN * DIMN];             // 2 base-256 limbs of W*2^16
__device__ __align__(16) int g_na[T_STEPS * BN];                        // active count per (t,row)
__device__ int g_nflag;
__device__ uint32_t g_flags[FLAG_CAP];

// ---------------- K0: exact base-256 limb split of W*2^16 (+ flag reset) ----------------
__global__ void k_split_w(const float* __restrict__ W) {
    int i = blockIdx.x * blockDim.x + threadIdx.x;
    if (i == 0) g_nflag = 0;
    if (i >= DIMN * DIMN) return;
    int v = (int)llrintf(W[i] * 65536.0f);        // |W|<0.45 -> |v| < 29500 (safe)
    int d0 = ((v + 128) & 255) - 128;             // balanced digit in [-128,127]
    int d1 = (v - d0) >> 8;                       // exact, |d1| <= 116
    g_Wl[i]               = (signed char)d0;
    g_Wl[DIMN * DIMN + i] = (signed char)d1;
}

// ---------------- K1: LIF1 (bit-exact) + per-row active counts ----------------
__global__ void k_lif1(const float* __restrict__ in) {
    int gt = blockIdx.x * blockDim.x + threadIdx.x;
    int bn = gt >> 5, lane = gt & 31;
    if (bn >= BN) return;
    int d0 = lane * 16;
    float v[16];
#pragma unroll
    for (int j = 0; j < 16; ++j) v[j] = 0.f;
#pragma unroll
    for (int t = 0; t < T_STEPS; ++t) {
        const float4* xp = reinterpret_cast<const float4*>(
            in + ((size_t)(t * BN + bn)) * 1024 + 512 + d0);
        uint32_t pk[4];
        int cnt = 0;
#pragma unroll
        for (int q = 0; q < 4; ++q) {
            float4 x = xp[q];
            float xv[4] = {x.x, x.y, x.z, x.w};
            uint32_t b = 0;
#pragma unroll
            for (int j = 0; j < 4; ++j) {
                int jj = q * 4 + j;
                v[jj] = v[jj] * 0.5f + xv[j];      // *0.5 exact -> bit-identical to ref
                int s = (v[jj] >= 1.0f) ? 1 : 0;
                v[jj] = s ? 0.f : v[jj];
                b |= (uint32_t)s << (8 * j);
                cnt += s;
            }
            pk[q] = b;
        }
        *reinterpret_cast<uint4*>(g_S + ((size_t)(t * BN + bn)) * 512 + d0) =
            make_uint4(pk[0], pk[1], pk[2], pk[3]);
#pragma unroll
        for (int off = 16; off; off >>= 1)
            cnt += __shfl_xor_sync(0xFFFFFFFF, cnt, off);
        if (lane == 0) g_na[t * BN + bn] = cnt;
    }
}

// ---------------- asm helpers ----------------
__device__ __forceinline__ uint32_t smem_u32(const void* p) {
    uint32_t r;
    asm("{ .reg .u64 t; cvta.to.shared.u64 t, %1; cvt.u32.u64 %0, t; }" : "=r"(r) : "l"(p));
    return r;
}
__device__ __forceinline__ void cp16(uint32_t saddr, const void* g) {
    asm volatile("cp.async.cg.shared.global [%0], [%1], 16;" :: "r"(saddr), "l"(g) : "memory");
}
#define CP_COMMIT() asm volatile("cp.async.commit_group;" ::: "memory")
#define CP_WAIT(n)  asm volatile("cp.async.wait_group %0;" :: "n"(n) : "memory")

__device__ __forceinline__ void ldm_x4(uint32_t* a, uint32_t addr) {
    asm volatile("ldmatrix.sync.aligned.m8n8.x4.shared.b16 {%0,%1,%2,%3}, [%4];"
                 : "=r"(a[0]), "=r"(a[1]), "=r"(a[2]), "=r"(a[3]) : "r"(addr));
}
__device__ __forceinline__ void mma_s8(int* c, const uint32_t* a, uint32_t b0, uint32_t b1) {
    asm volatile(
        "mma.sync.aligned.m16n8k32.row.col.s32.s8.s8.s32 "
        "{%0,%1,%2,%3}, {%4,%5,%6,%7}, {%8,%9}, {%0,%1,%2,%3};"
        : "+r"(c[0]), "+r"(c[1]), "+r"(c[2]), "+r"(c[3])
        : "r"(a[0]), "r"(a[1]), "r"(a[2]), "r"(a[3]), "r"(b0), "r"(b1));
}

// ---------------- K2: 2-limb exact GEMM + LIF2 + gated multiply + tie flagging ----------------
// CTA tile 128(bn) x 32(e), 256 threads, 2 CTAs/SM for barrier/epilogue overlap.
// 8 warps: wm = wid&3 (32 rows), wn = wid>>2 in {0,1} (16 cols).
#define M_TILE   128
#define N_TILE   32
#define K_CHUNK  64
#define B_LIMB_B (N_TILE * DIMN)              // 16384 per limb
#define B_BYTES  (2 * B_LIMB_B)               // 32768 (resident W limbs)
#define A_STAGE  (M_TILE * K_CHUNK)           // 8192
#define IN_OFF   (B_BYTES + 2 * A_STAGE)      // 49152: in-tile [128 x 32] f32 (16KB)
#define NA_OFF   (IN_OFF + M_TILE * N_TILE * 4)  // 65536: na[128]
#define SMEM_TOTAL (NA_OFF + 512)             // 66048

__device__ __forceinline__ void load_A(uint32_t sA, const signed char* __restrict__ gA, int tid) {
#pragma unroll
    for (int i = 0; i < 2; ++i) {
        int lin = tid + i * 256;
        int row = lin >> 2, ch = lin & 3;
        cp16(sA + (uint32_t)(row * 64 + ((ch ^ ((row >> 1) & 3)) * 16)),
             gA + (size_t)row * 512 + ch * 16);
    }
}

__global__ __launch_bounds__(256, 2)
void k_gemm_lif2(const float* __restrict__ in, const float* __restrict__ bvec,
                 float* __restrict__ out) {
    extern __shared__ char smem[];
    const uint32_t sB = smem_u32(smem);
    const uint32_t sAb = sB + B_BYTES;
    const int tid = threadIdx.x, wid = tid >> 5, lane = tid & 31;
    const int wm = wid & 3, wn = wid >> 2;     // wn in {0,1}
    const int bn0 = blockIdx.x * M_TILE;
    const int et0 = blockIdx.y * N_TILE;

    // ---- resident B: 2 limbs x [32 e-rows x 512 k-bytes], swizzled ----
#pragma unroll
    for (int i = 0; i < 8; ++i) {
        int lin = tid + i * 256;
        int limb = lin >> 10, rem = lin & 1023;
        int n = rem >> 5, kc = rem & 31;
        cp16(sB + (uint32_t)(limb * B_LIMB_B + n * 512 + ((kc ^ (n & 7)) * 16)),
             g_Wl + (size_t)limb * (DIMN * DIMN) + (size_t)(et0 + n) * 512 + kc * 16);
    }
    CP_COMMIT();

    load_A(sAb,           g_S + ((size_t)bn0) * 512 + 0 * 64, tid);
    CP_COMMIT();
    load_A(sAb + A_STAGE, g_S + ((size_t)bn0) * 512 + 1 * 64, tid);
    CP_COMMIT();

    float bb[2][2];
#pragma unroll
    for (int ng = 0; ng < 2; ++ng)
#pragma unroll
        for (int q = 0; q < 2; ++q)
            bb[ng][q] = bvec[et0 + wn * 16 + ng * 8 + 2 * (lane & 3) + q];

    const int lrow = lane & 15, lch = lane >> 4;
    const float* inS = (const float*)(smem + IN_OFF);
    const int*   naS = (const int*)(smem + NA_OFF);

    float v[2][2][4];
#pragma unroll
    for (int i = 0; i < 2; ++i)
#pragma unroll
        for (int ng = 0; ng < 2; ++ng)
#pragma unroll
            for (int e = 0; e < 4; ++e) v[i][ng][e] = 0.f;

    unsigned fl = 0;

#pragma unroll 1
    for (int t = 0; t < T_STEPS; ++t) {
        int acc[2][2][2][4];
#pragma unroll
        for (int l = 0; l < 2; ++l)
#pragma unroll
            for (int i = 0; i < 2; ++i)
#pragma unroll
                for (int ng = 0; ng < 2; ++ng)
#pragma unroll
                    for (int e = 0; e < 4; ++e) acc[l][i][ng][e] = 0;

#pragma unroll 1
        for (int c = 0; c < 8; ++c) {
            CP_WAIT(1);
            __syncthreads();
            const uint32_t sA = sAb + (uint32_t)((c & 1) * A_STAGE);

            uint32_t a[2][2][4];
#pragma unroll
            for (int i = 0; i < 2; ++i)
#pragma unroll
                for (int ks = 0; ks < 2; ++ks) {
                    int row = wm * 32 + i * 16 + lrow;
                    int ch = ks * 2 + lch;
                    ldm_x4(a[i][ks], sA + (uint32_t)(row * 64 + ((ch ^ ((row >> 1) & 3)) * 16)));
                }

#pragma unroll
            for (int l = 0; l < 2; ++l) {
#pragma unroll
                for (int ks = 0; ks < 2; ++ks) {
                    uint32_t bf[4];
                    int n = wn * 16 + lrow;
                    int kc = c * 4 + ks * 2 + lch;
                    ldm_x4(bf, sB + (uint32_t)(l * B_LIMB_B + n * 512 + ((kc ^ (n & 7)) * 16)));
#pragma unroll
                    for (int i = 0; i < 2; ++i) {
                        mma_s8(acc[l][i][0], a[i][ks], bf[0], bf[2]);
                        mma_s8(acc[l][i][1], a[i][ks], bf[1], bf[3]);
                    }
                }
            }
            __syncthreads();

            if (c == 0) {
                // prefetch this t's outputs-tile + na row into smem
                const float* gin = in + ((size_t)(t * BN + bn0)) * 1024 + et0;
#pragma unroll
                for (int i2 = 0; i2 < 4; ++i2) {
                    int lin = i2 * 256 + tid;
                    int r = lin >> 3, cg = lin & 7;
                    cp16(sB + (uint32_t)(IN_OFF + r * 128 + cg * 16),
                         gin + (size_t)r * 1024 + cg * 4);
                }
                if (tid < 32)
                    cp16(sB + (uint32_t)(NA_OFF + tid * 16), g_na + t * BN + bn0 + tid * 4);
            }
            int next = t * 8 + c + 2;
            if (next < 32) {
                int tn = next >> 3, cn = next & 7;
                load_A(sAb + (uint32_t)((c & 1) * A_STAGE),
                       g_S + ((size_t)(tn * BN + bn0)) * 512 + cn * 64, tid);
            }
            CP_COMMIT();
        }

        // ---- epilogue: exact reconstruction + bias + LIF2 + flag + gated multiply ----
#pragma unroll
        for (int i = 0; i < 2; ++i) {
#pragma unroll
            for (int h = 0; h < 2; ++h) {
                int rowl = wm * 32 + i * 16 + (lane >> 2) + h * 8;
                // hard bound on |v - v_ref|: quant (na*2^-17 half-ulp, x2 membrane) + chain
                float na = (float)naS[rowl];
                float tau = fmaf(na, 1.52587890625e-05f, 4e-4f);
#pragma unroll
                for (int ng = 0; ng < 2; ++ng) {
                    int coll = wn * 16 + ng * 8 + 2 * (lane & 3);
                    float s[2];
#pragma unroll
                    for (int q = 0; q < 2; ++q) {
                        int e = 2 * h + q;
                        float y = fmaf((float)acc[1][i][ng][e], 256.0f,
                                       (float)acc[0][i][ng][e])
                                  * 1.52587890625e-05f;                // * 2^-16, all exact
                        float g = y + bb[ng][q];
                        float vv = v[i][ng][e] * 0.5f + g;
                        float sp = (vv >= 1.0f) ? 1.0f : 0.0f;
                        v[i][ng][e] = vv * (1.0f - sp);
                        s[q] = sp;
                        if (fabsf(vv - 1.0f) < tau)
                            fl |= 1u << (i * 8 + ng * 4 + h * 2 + q);
                    }
                    const float2 o = *reinterpret_cast<const float2*>(
                        inS + rowl * N_TILE + coll);
                    size_t grow = (size_t)(t * BN) + bn0 + rowl;
                    float2 r;
                    r.x = o.x * s[0];
                    r.y = o.y * s[1];
                    *reinterpret_cast<float2*>(out + grow * 512 + et0 + coll) = r;
                }
            }
        }
    }

    if (fl) {
#pragma unroll
        for (int i = 0; i < 2; ++i)
#pragma unroll
            for (int ng = 0; ng < 2; ++ng)
#pragma unroll
                for (int h = 0; h < 2; ++h)
#pragma unroll
                    for (int q = 0; q < 2; ++q)
                        if (fl & (1u << (i * 8 + ng * 4 + h * 2 + q))) {
                            int row = bn0 + wm * 32 + i * 16 + (lane >> 2) + h * 8;
                            int col = et0 + wn * 16 + ng * 8 + 2 * (lane & 3) + q;
                            int idx = atomicAdd(&g_nflag, 1);
                            if (idx < FLAG_CAP)
                                g_flags[idx] = (uint32_t)(row * 512 + col);
                        }
    }
}

// ---------------- K3: fixup — replicate reference fp32 chain on flagged ties ----------------
// 4 independent per-t add-chains interleaved in registers (4-way ILP), W row loaded once.
__global__ __launch_bounds__(256)
void k_fixup(const float* __restrict__ in, const float* __restrict__ W,
             const float* __restrict__ bvec, float* __restrict__ out) {
    int n = g_nflag;
    if (n > FLAG_CAP) n = FLAG_CAP;
    for (int idx = blockIdx.x * blockDim.x + threadIdx.x; idx < n;
         idx += gridDim.x * blockDim.x) {
        uint32_t key = g_flags[idx];
        int bn = (int)(key >> 9), e = (int)(key & 511);
        const float4* w4 = reinterpret_cast<const float4*>(W + (size_t)e * 512);
        float bias = bvec[e];

        float acc[T_STEPS];
#pragma unroll
        for (int t = 0; t < T_STEPS; ++t) acc[t] = 0.f;

#pragma unroll 1
        for (int g16 = 0; g16 < 32; ++g16) {
            uint4 m[T_STEPS];
#pragma unroll
            for (int t = 0; t < T_STEPS; ++t)
                m[t] = reinterpret_cast<const uint4*>(
                    g_S + ((size_t)(t * BN + bn)) * 512)[g16];
            float4 wv[4];
#pragma unroll
            for (int u = 0; u < 4; ++u) wv[u] = w4[g16 * 4 + u];
#pragma unroll
            for (int u = 0; u < 4; ++u) {
                uint32_t mw[T_STEPS] = {
                    (&m[0].x)[u], (&m[1].x)[u], (&m[2].x)[u], (&m[3].x)[u]};
                const float wj[4] = {wv[u].x, wv[u].y, wv[u].z, wv[u].w};
#pragma unroll
                for (int j = 0; j < 4; ++j) {
#pragma unroll
                    for (int t = 0; t < T_STEPS; ++t)
                        acc[t] += ((mw[t] >> (8 * j)) & 1u) ? wj[j] : 0.0f;
                }
            }
        }

        float v = 0.f;
#pragma unroll
        for (int t = 0; t < T_STEPS; ++t) {
            float g = acc[t] + bias;
            float vv = v * 0.5f + g;
            float s = (vv >= 1.0f) ? 1.0f : 0.0f;
            v = vv * (1.0f - s);
            size_t grow = (size_t)(t * BN) + bn;
            out[grow * 512 + e] = in[grow * 1024 + e] * s;
        }
    }
}

// ---------------- launcher ----------------
extern "C" void kernel_launch(void* const* d_in, const int* in_sizes, int n_in,
                              void* d_out, int out_size) {
    const float* inputs = (const float*)d_in[0];   // [4,32,512,1024]
    const float* W      = (const float*)d_in[1];   // [512,512]
    const float* b      = (const float*)d_in[2];   // [512]
    float* out          = (float*)d_out;           // [4,32,512,512]

    cudaFuncSetAttribute(k_gemm_lif2, cudaFuncAttributeMaxDynamicSharedMemorySize, SMEM_TOTAL);

    k_split_w<<<(DIMN * DIMN + 255) / 256, 256>>>(W);
    k_lif1<<<(BN * 32 + 255) / 256, 256>>>(inputs);
    k_gemm_lif2<<<dim3(BN / M_TILE, DIMN / N_TILE), 256, SMEM_TOTAL>>>(inputs, b, out);
    k_fixup<<<768, 256>>>(inputs, W, b, out);
}